// round 6
// baseline (speedup 1.0000x reference)
#include <cuda_runtime.h>
#include <cuda_fp16.h>
#include <cstdint>

// out = x @ W^T  (GAT attention cancels: softmax rows sum to 1; the final
// einsum multiplies h by sum_j alpha = 1; adj, a_w are dead inputs).
//   M = 8192, N = 256, K = 256. A=x, B=W, both row-major K-minor (NT gemm).
//
// tcgen05 unavailable (.target sm_103); ldmatrix + mma.sync.m16n8k16 f16/f32.
// Latency-oriented: one full-K smem load (max MLP), ONE sync, pure MMA loop.
// BM=BN=64 -> 512 CTAs, 64KB smem/CTA, 3 CTAs/SM, 24 warps/SM.

#define THREADS 256
#define BM 64
#define BN 64
#define KGLOB 256
#define TILE_B 8192            // 64 rows x 128B (64 fp16) SW128 tile
#define SA_BYTES (4 * TILE_B)  // 32KB: A slice 64x256 fp16
#define SB_BYTES (4 * TILE_B)  // 32KB: B slice 64x256 fp16
#define SMEM_TOTAL (SA_BYTES + SB_BYTES)

__device__ __forceinline__ uint32_t smem_u32(const void* p) {
    uint32_t a;
    asm("{ .reg .u64 t; cvta.to.shared.u64 t, %1; cvt.u32.u64 %0, t; }" : "=r"(a) : "l"(p));
    return a;
}
__device__ __forceinline__ uint32_t swz(uint32_t off) { return off ^ ((off >> 3) & 0x70); }

__device__ __forceinline__ void ldsm4(uint32_t& r0, uint32_t& r1, uint32_t& r2, uint32_t& r3,
                                      uint32_t addr) {
    asm volatile("ldmatrix.sync.aligned.m8n8.x4.shared.b16 {%0,%1,%2,%3}, [%4];"
                 : "=r"(r0), "=r"(r1), "=r"(r2), "=r"(r3) : "r"(addr));
}

__device__ __forceinline__ void mma16816(float* c, const uint32_t* a, const uint32_t* b) {
    asm volatile("mma.sync.aligned.m16n8k16.row.col.f32.f16.f16.f32 "
                 "{%0,%1,%2,%3}, {%4,%5,%6,%7}, {%8,%9}, {%0,%1,%2,%3};"
                 : "+f"(c[0]), "+f"(c[1]), "+f"(c[2]), "+f"(c[3])
                 : "r"(a[0]), "r"(a[1]), "r"(a[2]), "r"(a[3]), "r"(b[0]), "r"(b[1]));
}

__device__ __forceinline__ uint32_t pack2(float x, float y) {
    __half2 h = __floats2half2_rn(x, y);
    return *reinterpret_cast<uint32_t*>(&h);
}

__global__ void __launch_bounds__(THREADS, 3)
gat_hmma_gemm(const float* __restrict__ A, const float* __restrict__ B, float* __restrict__ C)
{
    extern __shared__ __align__(1024) uint8_t smem[];
    uint8_t* sA = smem;
    uint8_t* sB = smem + SA_BYTES;

    const int tid = threadIdx.x;
    const int wid = tid >> 5;
    const int lid = tid & 31;
    const int bm = blockIdx.y, bn = blockIdx.x;
    const int wm = wid & 3;        // 4 warp rows of 16
    const int wn = wid >> 2;       // 2 warp cols of 32

    const uint32_t sAb = smem_u32(sA);
    const uint32_t sBb = smem_u32(sB);

    const float* Ag = A + (size_t)(bm * BM) * KGLOB;
    const float* Bg = B + (size_t)(bn * BN) * KGLOB;

    // ---- single full-K load: per k-chunk of 64, A and B are 64x16 float4 ----
    // per thread per chunk: 4 A-float4 + 4 B-float4; 4 chunks -> 32 LDG.128.
    {
        const int r  = tid >> 2;             // row 0..63 (4 threads per row)
        const int c4 = (tid & 3) * 4;        // float4 slot 0,4,8,12
        const uint32_t soff = swz((uint32_t)(r * 128 + c4 * 8));
        const size_t goff = (size_t)r * KGLOB + c4 * 4;
#pragma unroll
        for (int kc = 0; kc < 4; kc++) {
#pragma unroll
            for (int i = 0; i < 4; i++) {    // 4 float4 = 16 k-elems... per chunk row part
                // i indexes the remaining float4 within the 64-wide chunk row:
                // each thread covers slots c4..c4+3? No: 16 slots/row, 4 threads/row
                // -> thread handles slots {c4+0? } use stride-4 slots: c4 base + i? 
                ;
            }
            // (loop body below replaces the placeholder above)
            break;
        }
        // Explicit, correct version: 16 float4 per 64-elem chunk row, 4 threads/row
        // -> each thread takes slots (tid&3), (tid&3)+4, +8, +12.
#pragma unroll
        for (int kc = 0; kc < 4; kc++) {
            const float* Ac = Ag + kc * 64;
            const float* Bc = Bg + kc * 64;
            uint8_t* tA = sA + kc * TILE_B;
            uint8_t* tB = sB + kc * TILE_B;
#pragma unroll
            for (int i = 0; i < 4; i++) {
                int slot = (tid & 3) + i * 4;          // 0..15
                uint32_t so = swz((uint32_t)(r * 128 + slot * 8));
                float4 va = *(const float4*)(Ac + (size_t)r * KGLOB + slot * 4);
                uint2 pa; pa.x = pack2(va.x, va.y); pa.y = pack2(va.z, va.w);
                *(uint2*)(tA + so) = pa;
                float4 vb = *(const float4*)(Bc + (size_t)r * KGLOB + slot * 4);
                uint2 pb; pb.x = pack2(vb.x, vb.y); pb.y = pack2(vb.z, vb.w);
                *(uint2*)(tB + so) = pb;
            }
        }
        (void)soff; (void)goff;
    }
    __syncthreads();

    // ---- MMA: 16 k-steps of 16, no further syncs ----
    float acc[4][4];
#pragma unroll
    for (int j = 0; j < 4; j++)
#pragma unroll
        for (int k = 0; k < 4; k++) acc[j][k] = 0.f;

    const uint32_t a_row = (lid & 15);
    const uint32_t a_cb  = (lid >> 4) * 16;
    const uint32_t b_row = (lid & 7) + ((lid >> 4) << 3);
    const uint32_t b_cb  = ((lid >> 3) & 1) * 16;

#pragma unroll
    for (int ks = 0; ks < 16; ks++) {
        const uint32_t tile = (uint32_t)(ks >> 2) * TILE_B;
        const uint32_t kb = (uint32_t)(ks & 3) * 32;

        uint32_t a[4];
        ldsm4(a[0], a[1], a[2], a[3],
              sAb + tile + swz((wm * 16 + a_row) * 128 + kb + a_cb));

        uint32_t b[4][2];
#pragma unroll
        for (int ntp = 0; ntp < 2; ntp++) {
            ldsm4(b[2 * ntp][0], b[2 * ntp][1], b[2 * ntp + 1][0], b[2 * ntp + 1][1],
                  sBb + tile + swz((wn * 32 + ntp * 16 + b_row) * 128 + kb + b_cb));
        }
#pragma unroll
        for (int nt = 0; nt < 4; nt++)
            mma16816(acc[nt], a, b[nt]);
    }

    // ---- epilogue ----
    const int g = lid >> 2, tig = lid & 3;
#pragma unroll
    for (int nt = 0; nt < 4; nt++) {
        int row = bm * BM + wm * 16 + g;
        int col = bn * BN + wn * 32 + nt * 8 + 2 * tig;
        *(float2*)(C + (size_t)row * 256 + col) = make_float2(acc[nt][0], acc[nt][1]);
        *(float2*)(C + (size_t)(row + 8) * 256 + col) = make_float2(acc[nt][2], acc[nt][3]);
    }
}

extern "C" void kernel_launch(void* const* d_in, const int* in_sizes, int n_in,
                              void* d_out, int out_size)
{
    const float* x = (const float*)d_in[0];
    const float* W = (const float*)d_in[2];
    float* out = (float*)d_out;

    cudaFuncSetAttribute(gat_hmma_gemm, cudaFuncAttributeMaxDynamicSharedMemorySize, SMEM_TOTAL);
    dim3 grid(256 / BN, 8192 / BM);   // (4, 128) = 512 CTAs
    gat_hmma_gemm<<<grid, THREADS, SMEM_TOTAL>>>(x, W, out);
}

// round 7
// speedup vs baseline: 1.3476x; 1.3476x over previous
#include <cuda_runtime.h>
#include <cuda_fp16.h>
#include <cstdint>

// out = x @ W^T (GAT attention cancels: softmax rows sum to 1, final einsum
// multiplies h by sum_j alpha = 1; adj/a_w dead).  M=8192, N=256, K=256, NT.
//
// Two-kernel plan (tcgen05 unavailable under .target sm_103):
//   1) convert x, W fp32 -> fp16 scratch (streaming)
//   2) cp.async double-buffered ldmatrix+mma.m16n8k16 GEMM, fp32 accum

#define THREADS 256
#define BM 64
#define BN 128
#define KGLOB 256
#define NCHUNK 4           // K chunks of 64
#define A_STAGE_B 8192     // 64 rows x 128B
#define B_STAGE_B 16384    // 128 rows x 128B
#define STAGE_B (A_STAGE_B + B_STAGE_B)
#define SMEM_TOTAL (2 * STAGE_B)

__device__ __align__(16) __half g_xh[8192 * 256];
__device__ __align__(16) __half g_wh[256 * 256];

__device__ __forceinline__ uint32_t smem_u32(const void* p) {
    uint32_t a;
    asm("{ .reg .u64 t; cvta.to.shared.u64 t, %1; cvt.u32.u64 %0, t; }" : "=r"(a) : "l"(p));
    return a;
}
__device__ __forceinline__ uint32_t swz(uint32_t off) { return off ^ ((off >> 3) & 0x70); }

__device__ __forceinline__ void cp16(uint32_t dst, const void* src) {
    asm volatile("cp.async.cg.shared.global [%0], [%1], 16;" :: "r"(dst), "l"(src) : "memory");
}
__device__ __forceinline__ void cp_commit() {
    asm volatile("cp.async.commit_group;" ::: "memory");
}
template <int N>
__device__ __forceinline__ void cp_wait() {
    asm volatile("cp.async.wait_group %0;" :: "n"(N) : "memory");
}

__device__ __forceinline__ void ldsm4(uint32_t& r0, uint32_t& r1, uint32_t& r2, uint32_t& r3,
                                      uint32_t addr) {
    asm volatile("ldmatrix.sync.aligned.m8n8.x4.shared.b16 {%0,%1,%2,%3}, [%4];"
                 : "=r"(r0), "=r"(r1), "=r"(r2), "=r"(r3) : "r"(addr));
}
__device__ __forceinline__ void mma16816(float* c, const uint32_t* a, const uint32_t* b) {
    asm volatile("mma.sync.aligned.m16n8k16.row.col.f32.f16.f16.f32 "
                 "{%0,%1,%2,%3}, {%4,%5,%6,%7}, {%8,%9}, {%0,%1,%2,%3};"
                 : "+f"(c[0]), "+f"(c[1]), "+f"(c[2]), "+f"(c[3])
                 : "r"(a[0]), "r"(a[1]), "r"(a[2]), "r"(a[3]), "r"(b[0]), "r"(b[1]));
}
__device__ __forceinline__ uint32_t pack2(float x, float y) {
    __half2 h = __floats2half2_rn(x, y);
    return *reinterpret_cast<uint32_t*>(&h);
}

// ---------------- convert: fp32 -> fp16 ----------------
__global__ void __launch_bounds__(256)
cvt_kernel(const float4* __restrict__ in, int n4, int which)
{
    uint2* out = which ? (uint2*)g_wh : (uint2*)g_xh;
    int i = blockIdx.x * 256 + threadIdx.x;
    if (i < n4) {
        float4 v = in[i];
        uint2 p;
        p.x = pack2(v.x, v.y);
        p.y = pack2(v.z, v.w);
        out[i] = p;
    }
}

// ---------------- GEMM ----------------
__global__ void __launch_bounds__(THREADS)
gat_gemm2(float* __restrict__ C)
{
    extern __shared__ __align__(1024) uint8_t smem[];

    const int tid = threadIdx.x;
    const int wid = tid >> 5;
    const int lid = tid & 31;
    const int bm = blockIdx.y, bn = blockIdx.x;
    const int wm = wid & 1;          // 2 warp rows of 32
    const int wn = wid >> 1;         // 4 warp cols of 32

    const __half* Ag = g_xh + (size_t)(bm * BM) * KGLOB;
    const __half* Bg = g_wh + (size_t)(bn * BN) * KGLOB;

    // precompute per-thread cp.async coordinates
    const int ch_r  = tid >> 3;       // base row (A: +0/ +32? no: chunks below)
    const int ch_sl = tid & 7;        // 16B slot in row

    auto load_stage = [&](int c, int s) {
        uint8_t* base = smem + s * STAGE_B;
        // A: 512 chunks (64 rows x 8 slots), 2 per thread
#pragma unroll
        for (int i = 0; i < 2; i++) {
            int r = ch_r + i * 32;
            uint32_t dst = smem_u32(base + swz((uint32_t)(r * 128 + ch_sl * 16)));
            cp16(dst, Ag + (size_t)r * KGLOB + c * 64 + ch_sl * 8);
        }
        // B: 1024 chunks (128 rows x 8 slots), 4 per thread
#pragma unroll
        for (int i = 0; i < 4; i++) {
            int r = ch_r + i * 32;
            uint32_t dst = smem_u32(base + A_STAGE_B + swz((uint32_t)(r * 128 + ch_sl * 16)));
            cp16(dst, Bg + (size_t)r * KGLOB + c * 64 + ch_sl * 8);
        }
        cp_commit();
    };

    float acc[2][4][4];
#pragma unroll
    for (int i = 0; i < 2; i++)
#pragma unroll
        for (int j = 0; j < 4; j++)
#pragma unroll
            for (int k = 0; k < 4; k++) acc[i][j][k] = 0.f;

    const uint32_t a_row = (lid & 15);
    const uint32_t a_cb  = (lid >> 4) * 16;
    const uint32_t b_row = (lid & 7) + ((lid >> 4) << 3);
    const uint32_t b_cb  = ((lid >> 3) & 1) * 16;
    const uint32_t sAb = smem_u32(smem);
    const uint32_t sBb = sAb + A_STAGE_B;

    load_stage(0, 0);
    load_stage(1, 1);

#pragma unroll
    for (int c = 0; c < NCHUNK; c++) {
        if (c < NCHUNK - 1) cp_wait<1>(); else cp_wait<0>();
        __syncthreads();

        const uint32_t st = (uint32_t)(c & 1) * STAGE_B;
#pragma unroll
        for (int ks = 0; ks < 4; ks++) {
            const uint32_t kb = (uint32_t)ks * 32;
            uint32_t a[2][4];
#pragma unroll
            for (int mt = 0; mt < 2; mt++)
                ldsm4(a[mt][0], a[mt][1], a[mt][2], a[mt][3],
                      sAb + st + swz((wm * 32 + mt * 16 + a_row) * 128 + kb + a_cb));
            uint32_t b[4][2];
#pragma unroll
            for (int ntp = 0; ntp < 2; ntp++)
                ldsm4(b[2 * ntp][0], b[2 * ntp][1], b[2 * ntp + 1][0], b[2 * ntp + 1][1],
                      sBb + st + swz((wn * 32 + ntp * 16 + b_row) * 128 + kb + b_cb));
#pragma unroll
            for (int mt = 0; mt < 2; mt++)
#pragma unroll
                for (int nt = 0; nt < 4; nt++)
                    mma16816(acc[mt][nt], a[mt], b[nt]);
        }
        __syncthreads();
        if (c + 2 < NCHUNK) load_stage(c + 2, c & 1);
    }

    // epilogue: fp32 float2 stores
    const int g = lid >> 2, tig = lid & 3;
#pragma unroll
    for (int mt = 0; mt < 2; mt++) {
#pragma unroll
        for (int nt = 0; nt < 4; nt++) {
            int row = bm * BM + wm * 32 + mt * 16 + g;
            int col = bn * BN + wn * 32 + nt * 8 + 2 * tig;
            *(float2*)(C + (size_t)row * 256 + col) = make_float2(acc[mt][nt][0], acc[mt][nt][1]);
            *(float2*)(C + (size_t)(row + 8) * 256 + col) = make_float2(acc[mt][nt][2], acc[mt][nt][3]);
        }
    }
}

extern "C" void kernel_launch(void* const* d_in, const int* in_sizes, int n_in,
                              void* d_out, int out_size)
{
    const float* x = (const float*)d_in[0];
    const float* W = (const float*)d_in[2];
    float* out = (float*)d_out;

    // convert x: 8192*256 = 2,097,152 elems = 524,288 float4
    cvt_kernel<<<2048, 256>>>((const float4*)x, 524288, 0);
    // convert W: 256*256 = 65,536 elems = 16,384 float4
    cvt_kernel<<<64, 256>>>((const float4*)W, 16384, 1);

    cudaFuncSetAttribute(gat_gemm2, cudaFuncAttributeMaxDynamicSharedMemorySize, SMEM_TOTAL);
    dim3 grid(256 / BN, 8192 / BM);   // (2, 128) = 256 CTAs
    gat_gemm2<<<grid, THREADS, SMEM_TOTAL>>>(out);
}